// round 4
// baseline (speedup 1.0000x reference)
#include <cuda_runtime.h>
#include <math.h>

// ---------------- problem constants ----------------
#define NND     25000
#define INDIM   128
#define HID     256
#define NHEADS  4
#define HEADDIM 64
#define NLAYERS 3
#define NE      500000
#define ETOT    (NE + NND)   // reference appends self-loops

// ---------------- device scratch (static, no allocation) ----------------
__device__ float g_h   [NND * HID];
__device__ float g_xl  [NND * HID];
__device__ float g_xr  [NND * HID];
__device__ float g_skip[NND * HID];
__device__ float g_tmp [NND * HID];
__device__ int   g_deg [NND];
__device__ int   g_off [NND + 1];
__device__ int   g_cur [NND];
__device__ int   g_csr [ETOT];
__device__ int   g_is64;

// buffer ids: 0=h 1=xl 2=xr 3=skip 4=tmp  (resolved DEVICE-side only)
__device__ __forceinline__ float* buf_ptr(int id) {
    switch (id) {
        case 0: return g_h;
        case 1: return g_xl;
        case 2: return g_xr;
        case 3: return g_skip;
        default: return g_tmp;
    }
}

// edge_index dtype is declared int64 in the reference, but JAX default config
// (x64 disabled) silently produces int32. Detect device-side: if truly int64
// with values < 2^31, every odd 32-bit word is 0.
__global__ void detect_kernel(const void* ei) {
    if (threadIdx.x == 0 && blockIdx.x == 0) {
        const int* w = (const int*)ei;
        int nz = 0;
        #pragma unroll
        for (int k = 0; k < 64; k++) nz |= w[2 * k + 1];
        g_is64 = (nz == 0) ? 1 : 0;
    }
}

__device__ __forceinline__ int load_idx(const void* ei, long long pos) {
    if (g_is64) return (int)((const long long*)ei)[pos];
    return ((const int*)ei)[pos];
}

// ---------------- CSR construction ----------------
__global__ void zero_deg_kernel() {
    int i = blockIdx.x * blockDim.x + threadIdx.x;
    if (i < NND) g_deg[i] = 0;
}

__global__ void count_kernel(const void* __restrict__ ei) {
    int e = blockIdx.x * blockDim.x + threadIdx.x;
    if (e >= ETOT) return;
    int dst = (e < NE) ? load_idx(ei, (long long)NE + e) : (e - NE);
    atomicAdd(&g_deg[dst], 1);
}

__global__ void scan_kernel() {
    __shared__ int sh[1024];
    int run = 0;
    for (int base = 0; base < NND; base += 1024) {
        int idx = base + threadIdx.x;
        int v = (idx < NND) ? g_deg[idx] : 0;
        sh[threadIdx.x] = v;
        __syncthreads();
        #pragma unroll
        for (int d = 1; d < 1024; d <<= 1) {
            int t = (threadIdx.x >= d) ? sh[threadIdx.x - d] : 0;
            __syncthreads();
            sh[threadIdx.x] += t;
            __syncthreads();
        }
        if (idx < NND) {
            int excl = run + sh[threadIdx.x] - v;
            g_off[idx] = excl;
            g_cur[idx] = excl;
        }
        run += sh[1023];
        __syncthreads();
    }
    if (threadIdx.x == 0) g_off[NND] = run;
}

__global__ void fill_kernel(const void* __restrict__ ei) {
    int e = blockIdx.x * blockDim.x + threadIdx.x;
    if (e >= ETOT) return;
    int src, dst;
    if (e < NE) { src = load_idx(ei, e); dst = load_idx(ei, (long long)NE + e); }
    else        { src = e - NE;          dst = e - NE; }
    int pos = atomicAdd(&g_cur[dst], 1);
    g_csr[pos] = src;
}

// ---------------- SGEMM: C[N,M] = A[N,K] * B[K,M] (+bias)(+relu) ----------------
// BM=128 BN=128 BK=8, 256 threads, 8x8 per thread
// aId < 0: A = Aext (external input). cId selects internal scratch buffer.
// DUAL=1: blockIdx.y in [0,4): y<2 -> (B0 -> cId), y>=2 -> (B1 -> cId2)
template <int EPI, int DUAL>  // EPI: 0 = none, 2 = +bias,relu
__global__ __launch_bounds__(256)
void sgemm_kernel(const float* __restrict__ Aext, int aId,
                  const float* __restrict__ B0, const float* __restrict__ B1,
                  const float* __restrict__ bias, int cId, int cId2,
                  int Nrows, int K, int M) {
    const float* A = (aId < 0) ? Aext : buf_ptr(aId);
    int bc = blockIdx.y;
    const float* B = B0;
    float* C;
    if (DUAL) {
        if (bc >= 2) { B = B1; C = buf_ptr(cId2); bc -= 2; }
        else         { C = buf_ptr(cId); }
    } else {
        C = buf_ptr(cId);
    }

    __shared__ float As[8][128];
    __shared__ float Bs[8][128];

    const int tid = threadIdx.x;
    const int br = blockIdx.x;
    const int tx = tid & 15;          // 0..15  (col tile)
    const int ty = tid >> 4;          // 0..15  (row tile)

    const int rowA  = br * 128 + (tid >> 1);
    const int colA4 = (tid & 1) * 4;
    const int rowB  = tid >> 5;       // 0..7
    const int colBl = (tid & 31) * 4; // 0..124
    const int colB  = bc * 128 + colBl;

    float acc[8][8];
    #pragma unroll
    for (int m = 0; m < 8; m++)
        #pragma unroll
        for (int n = 0; n < 8; n++) acc[m][n] = 0.f;

    for (int k0 = 0; k0 < K; k0 += 8) {
        float4 av = make_float4(0.f, 0.f, 0.f, 0.f);
        if (rowA < Nrows)
            av = *(const float4*)(A + (size_t)rowA * K + k0 + colA4);
        As[colA4 + 0][tid >> 1] = av.x;
        As[colA4 + 1][tid >> 1] = av.y;
        As[colA4 + 2][tid >> 1] = av.z;
        As[colA4 + 3][tid >> 1] = av.w;

        float4 bv = *(const float4*)(B + (size_t)(k0 + rowB) * M + colB);
        *(float4*)&Bs[rowB][colBl] = bv;
        __syncthreads();

        #pragma unroll
        for (int kk = 0; kk < 8; kk++) {
            float aR[8], bR[8];
            #pragma unroll
            for (int m = 0; m < 8; m++) aR[m] = As[kk][ty * 8 + m];
            #pragma unroll
            for (int n = 0; n < 8; n++) bR[n] = Bs[kk][tx * 8 + n];
            #pragma unroll
            for (int m = 0; m < 8; m++)
                #pragma unroll
                for (int n = 0; n < 8; n++)
                    acc[m][n] = fmaf(aR[m], bR[n], acc[m][n]);
        }
        __syncthreads();
    }

    #pragma unroll
    for (int m = 0; m < 8; m++) {
        int row = br * 128 + ty * 8 + m;
        if (row >= Nrows) continue;
        #pragma unroll
        for (int n = 0; n < 8; n += 4) {
            int col = bc * 128 + tx * 8 + n;
            float4 v = make_float4(acc[m][n], acc[m][n + 1], acc[m][n + 2], acc[m][n + 3]);
            if (EPI >= 1) {
                v.x += bias[col]; v.y += bias[col + 1];
                v.z += bias[col + 2]; v.w += bias[col + 3];
            }
            if (EPI == 2) {
                v.x = fmaxf(v.x, 0.f); v.y = fmaxf(v.y, 0.f);
                v.z = fmaxf(v.z, 0.f); v.w = fmaxf(v.w, 0.f);
            }
            *(float4*)(C + (size_t)row * M + col) = v;
        }
    }
}

// ---------------- fused GATv2 edge aggregation + bias + skip + LN + relu ----------------
// one warp per node; lane owns channels [lane*8, lane*8+8), head = lane/8
__global__ __launch_bounds__(256)
void gat_edge_ln_kernel(const float* __restrict__ att_l,
                        const float* __restrict__ gatb_l,
                        const float* __restrict__ lng_l,
                        const float* __restrict__ lnb_l) {
    const int warp = threadIdx.x >> 5;
    const int lane = threadIdx.x & 31;
    const int i = blockIdx.x * 8 + warp;
    if (i >= NND) return;

    const int head = lane >> 3;
    const int cbase = lane * 8;

    // xr[i] and att in registers
    float xr[8], attv[8];
    {
        const float4* p = (const float4*)(g_xr + (size_t)i * HID + cbase);
        float4 a = p[0], b = p[1];
        xr[0]=a.x; xr[1]=a.y; xr[2]=a.z; xr[3]=a.w;
        xr[4]=b.x; xr[5]=b.y; xr[6]=b.z; xr[7]=b.w;
        #pragma unroll
        for (int k = 0; k < 8; k++)
            attv[k] = att_l[head * HEADDIM + (lane & 7) * 8 + k];
    }

    float m = -INFINITY, s = 0.f;
    float accv[8];
    #pragma unroll
    for (int k = 0; k < 8; k++) accv[k] = 0.f;

    const int jb = g_off[i], je = g_off[i + 1];
    for (int j = jb; j < je; j++) {
        const int src = g_csr[j];
        const float4* xp = (const float4*)(g_xl + (size_t)src * HID + cbase);
        float4 a = xp[0], b = xp[1];
        float xlv[8] = {a.x, a.y, a.z, a.w, b.x, b.y, b.z, b.w};

        float partial = 0.f;
        #pragma unroll
        for (int k = 0; k < 8; k++) {
            float t = xlv[k] + xr[k];
            t = (t > 0.f) ? t : 0.2f * t;          // leaky_relu 0.2
            partial = fmaf(t, attv[k], partial);
        }
        partial += __shfl_down_sync(0xffffffffu, partial, 4);
        partial += __shfl_down_sync(0xffffffffu, partial, 2);
        partial += __shfl_down_sync(0xffffffffu, partial, 1);
        const float logit = __shfl_sync(0xffffffffu, partial, lane & ~7);

        // online softmax, per-head state replicated across the 8-lane group
        const float nm = fmaxf(m, logit);
        const float scale = __expf(m - nm);         // m=-inf first iter -> 0
        const float p = __expf(logit - nm);
        s = fmaf(s, scale, p);
        m = nm;
        #pragma unroll
        for (int k = 0; k < 8; k++)
            accv[k] = fmaf(accv[k], scale, p * xlv[k]);
    }

    const float inv = 1.f / fmaxf(s, 1e-16f);

    // v = agg + gat_b + skip(relu'd already)
    float v[8];
    {
        const float4* sp = (const float4*)(g_skip + (size_t)i * HID + cbase);
        float4 a = sp[0], b = sp[1];
        float sk[8] = {a.x, a.y, a.z, a.w, b.x, b.y, b.z, b.w};
        #pragma unroll
        for (int k = 0; k < 8; k++)
            v[k] = accv[k] * inv + gatb_l[cbase + k] + sk[k];
    }

    // LayerNorm over 256 channels (warp owns whole row)
    float lsum = 0.f;
    #pragma unroll
    for (int k = 0; k < 8; k++) lsum += v[k];
    #pragma unroll
    for (int d = 16; d > 0; d >>= 1) lsum += __shfl_xor_sync(0xffffffffu, lsum, d);
    const float mu = lsum * (1.f / HID);

    float vsum = 0.f;
    #pragma unroll
    for (int k = 0; k < 8; k++) { float ddd = v[k] - mu; vsum = fmaf(ddd, ddd, vsum); }
    #pragma unroll
    for (int d = 16; d > 0; d >>= 1) vsum += __shfl_xor_sync(0xffffffffu, vsum, d);
    const float rstd = rsqrtf(vsum * (1.f / HID) + 1e-5f);

    float o[8];
    #pragma unroll
    for (int k = 0; k < 8; k++) {
        float t = lng_l[cbase + k] * (v[k] - mu) * rstd + lnb_l[cbase + k];
        o[k] = fmaxf(t, 0.f);
    }
    float4* hp = (float4*)(g_h + (size_t)i * HID + cbase);
    hp[0] = make_float4(o[0], o[1], o[2], o[3]);
    hp[1] = make_float4(o[4], o[5], o[6], o[7]);
}

// ---------------- output head: out[i] = dot(tmp[i,:], W2) + b2 ----------------
__global__ __launch_bounds__(256)
void out_head_kernel(const float* __restrict__ W2, const float* __restrict__ b2,
                     float* __restrict__ out) {
    const int warp = threadIdx.x >> 5;
    const int lane = threadIdx.x & 31;
    const int i = blockIdx.x * 8 + warp;
    if (i >= NND) return;

    const float4* tp = (const float4*)(g_tmp + (size_t)i * HID + lane * 8);
    const float4* wp = (const float4*)(W2 + lane * 8);
    float4 t0 = tp[0], t1 = tp[1];
    float4 w0 = wp[0], w1 = wp[1];
    float dsum = t0.x * w0.x + t0.y * w0.y + t0.z * w0.z + t0.w * w0.w
               + t1.x * w1.x + t1.y * w1.y + t1.z * w1.z + t1.w * w1.w;
    #pragma unroll
    for (int d = 16; d > 0; d >>= 1) dsum += __shfl_xor_sync(0xffffffffu, dsum, d);
    if (lane == 0) out[i] = dsum + b2[0];
}

// ---------------- launch ----------------
extern "C" void kernel_launch(void* const* d_in, const int* in_sizes, int n_in,
                              void* d_out, int out_size) {
    const float* x      = (const float*)d_in[0];
    const void*  ei     = d_in[1];                 // int32 OR int64 (detected on device)
    // d_in[2] batch, d_in[3] adj_matrices: unused
    const float* enc_W  = (const float*)d_in[4];
    const float* enc_b  = (const float*)d_in[5];
    const float* Wl     = (const float*)d_in[6];
    const float* Wr     = (const float*)d_in[7];
    const float* att    = (const float*)d_in[8];
    const float* gat_b  = (const float*)d_in[9];
    const float* skip_W = (const float*)d_in[10];
    const float* skip_b = (const float*)d_in[11];
    const float* ln_g   = (const float*)d_in[12];
    const float* ln_b   = (const float*)d_in[13];
    const float* out_W1 = (const float*)d_in[14];
    const float* out_b1 = (const float*)d_in[15];
    const float* out_W2 = (const float*)d_in[16];
    const float* out_b2 = (const float*)d_in[17];
    float* out = (float*)d_out;

    // CSR build (dtype-detected, reused across layers)
    detect_kernel<<<1, 32>>>(ei);
    zero_deg_kernel<<<(NND + 511) / 512, 512>>>();
    count_kernel<<<(ETOT + 511) / 512, 512>>>(ei);
    scan_kernel<<<1, 1024>>>();
    fill_kernel<<<(ETOT + 511) / 512, 512>>>(ei);

    const dim3 gemm_grid((NND + 127) / 128, HID / 128);       // 196 x 2
    const dim3 gemm_grid2((NND + 127) / 128, 2 * HID / 128);  // 196 x 4 (dual)

    // encoder: h = relu(x @ enc_W + enc_b)
    sgemm_kernel<2, 0><<<gemm_grid, 256>>>(x, -1, enc_W, nullptr, enc_b, 0, 0,
                                           NND, INDIM, HID);

    for (int L = 0; L < NLAYERS; L++) {
        const float* WlL  = Wl + (size_t)L * HID * HID;
        const float* WrL  = Wr + (size_t)L * HID * HID;
        const float* skWL = skip_W + (size_t)L * HID * HID;

        // xl = h@Wl, xr = h@Wr in one launch (dual-B)
        sgemm_kernel<0, 1><<<gemm_grid2, 256>>>(nullptr, 0, WlL, WrL, nullptr, 1, 2,
                                                NND, HID, HID);
        // skip = relu(h@skip_W + skip_b)
        sgemm_kernel<2, 0><<<gemm_grid, 256>>>(nullptr, 0, skWL, nullptr,
                                               skip_b + L * HID, 3, 3, NND, HID, HID);

        gat_edge_ln_kernel<<<(NND + 7) / 8, 256>>>(
            att + L * NHEADS * HEADDIM, gat_b + L * HID,
            ln_g + L * HID, ln_b + L * HID);
    }

    // output head
    sgemm_kernel<2, 0><<<gemm_grid, 256>>>(nullptr, 0, out_W1, nullptr, out_b1, 4, 4,
                                           NND, HID, HID);
    out_head_kernel<<<(NND + 7) / 8, 256>>>(out_W2, out_b2, out);

    (void)in_sizes; (void)n_in; (void)out_size;
}